// round 6
// baseline (speedup 1.0000x reference)
#include <cuda_runtime.h>
#include <cuda_bf16.h>
#include <cstdint>

#define H_     128
#define CIN_   64
#define O_     16
#define F2_    16
#define NT_    32768
#define TILES_ 2
#define NTH_   512
#define EPS_   1e-5f
#define SLOPE_ 0.01f

// ---- shared memory byte offsets ----
#define SM_W0  0          // [4][16][32] uint4 = 32768   {bh.x,bh.y,bl.x,bl.y}
#define SM_W1  32768      // [8][16][32] uint4 = 65536
#define SM_W2  98304      // [8][2][32]  uint4 = 8192
#define SM_VEC 106496     // 784 floats: b0,g0,be0,b1,g1,be1 (128 each) + b2 (16)
#define SM_AL  109632     // [16 warps][8 s][32 lanes] uint4 = 65536
#define SMEM_BYTES (109632 + 65536)

__device__ __forceinline__ float leaky_(float v) { return v >= 0.f ? v : SLOPE_ * v; }

// pack two fp32 -> bf16x2 hi (low half = y0) and bf16x2 lo (residuals)
__device__ __forceinline__ void split2(float y0, float y1, uint32_t& hp, uint32_t& lp) {
    uint32_t h;
    asm("cvt.rn.bf16x2.f32 %0, %1, %2;" : "=r"(h) : "f"(y1), "f"(y0));
    __nv_bfloat162 hb = *reinterpret_cast<__nv_bfloat162*>(&h);
    float r0 = y0 - __bfloat162float(hb.x);
    float r1 = y1 - __bfloat162float(hb.y);
    asm("cvt.rn.bf16x2.f32 %0, %1, %2;" : "=r"(lp) : "f"(r1), "f"(r0));
    hp = h;
}

#define MMA2(dd, aa, b0, b1)                                                   \
    asm volatile("mma.sync.aligned.m16n8k16.row.col.f32.bf16.bf16.f32 "       \
                 "{%0,%1,%2,%3}, {%4,%5,%6,%7}, {%8,%9}, {%0,%1,%2,%3};"      \
                 : "+f"((dd)[0]), "+f"((dd)[1]), "+f"((dd)[2]), "+f"((dd)[3]) \
                 : "r"((aa)[0]), "r"((aa)[1]), "r"((aa)[2]), "r"((aa)[3]),    \
                   "r"(b0), "r"(b1))

// LayerNorm + repack: hi fragments -> ah regs, lo fragments -> SMEM (myAL[s*32]).
__device__ __forceinline__ void ln_repack(float (&d)[16][4],
                                          const float* __restrict__ bias,
                                          const float* __restrict__ gam,
                                          const float* __restrict__ bet,
                                          uint32_t (&ah)[8][4],
                                          uint4* __restrict__ myAL,
                                          int t) {
    float s1a = 0.f, s2a = 0.f, s1b = 0.f, s2b = 0.f;
#pragma unroll
    for (int j = 0; j < 16; j++) {
        float2 bb = *(const float2*)(bias + 8 * j + 2 * t);
        float v0 = leaky_(d[j][0] + bb.x);
        float v1 = leaky_(d[j][1] + bb.y);
        float v2 = leaky_(d[j][2] + bb.x);
        float v3 = leaky_(d[j][3] + bb.y);
        d[j][0] = v0; d[j][1] = v1; d[j][2] = v2; d[j][3] = v3;
        s1a += v0 + v1; s2a += v0 * v0 + v1 * v1;
        s1b += v2 + v3; s2b += v2 * v2 + v3 * v3;
    }
#pragma unroll
    for (int off = 1; off <= 2; off <<= 1) {
        s1a += __shfl_xor_sync(0xffffffffu, s1a, off);
        s2a += __shfl_xor_sync(0xffffffffu, s2a, off);
        s1b += __shfl_xor_sync(0xffffffffu, s1b, off);
        s2b += __shfl_xor_sync(0xffffffffu, s2b, off);
    }
    float mua = s1a * (1.f / 128.f);
    float rsa = rsqrtf(fmaxf(s2a * (1.f / 128.f) - mua * mua, 0.f) + EPS_);
    float mub = s1b * (1.f / 128.f);
    float rsb = rsqrtf(fmaxf(s2b * (1.f / 128.f) - mub * mub, 0.f) + EPS_);
#pragma unroll
    for (int s = 0; s < 8; s++) {
        int j0 = 2 * s, j1 = 2 * s + 1;
        float2 g0v = *(const float2*)(gam + 8 * j0 + 2 * t);
        float2 e0v = *(const float2*)(bet + 8 * j0 + 2 * t);
        float2 g1v = *(const float2*)(gam + 8 * j1 + 2 * t);
        float2 e1v = *(const float2*)(bet + 8 * j1 + 2 * t);
        uint32_t l0, l1, l2, l3;
        float y0 = (d[j0][0] - mua) * rsa * g0v.x + e0v.x;
        float y1 = (d[j0][1] - mua) * rsa * g0v.y + e0v.y;
        split2(y0, y1, ah[s][0], l0);
        y0 = (d[j0][2] - mub) * rsb * g0v.x + e0v.x;
        y1 = (d[j0][3] - mub) * rsb * g0v.y + e0v.y;
        split2(y0, y1, ah[s][1], l1);
        y0 = (d[j1][0] - mua) * rsa * g1v.x + e1v.x;
        y1 = (d[j1][1] - mua) * rsa * g1v.y + e1v.y;
        split2(y0, y1, ah[s][2], l2);
        y0 = (d[j1][2] - mub) * rsb * g1v.x + e1v.x;
        y1 = (d[j1][3] - mub) * rsb * g1v.y + e1v.y;
        split2(y0, y1, ah[s][3], l3);
        myAL[s * 32] = make_uint4(l0, l1, l2, l3);
    }
}

__global__ __launch_bounds__(NTH_, 1)
void film_mma_kernel(const float* __restrict__ x,
                     const float* __restrict__ W0, const float* __restrict__ b0,
                     const float* __restrict__ g0, const float* __restrict__ be0,
                     const float* __restrict__ W1, const float* __restrict__ b1,
                     const float* __restrict__ g1, const float* __restrict__ be1,
                     const float* __restrict__ W2, const float* __restrict__ b2,
                     float* __restrict__ out) {
    extern __shared__ char sp[];
    uint4* f0 = (uint4*)(sp + SM_W0);
    uint4* f1 = (uint4*)(sp + SM_W1);
    uint4* f2 = (uint4*)(sp + SM_W2);
    float* sVec = (float*)(sp + SM_VEC);
    uint4* sAL = (uint4*)(sp + SM_AL);
    // uint2 views: element 2*i = {hi0,hi1}, 2*i+1 = {lo0,lo1}
    const uint2* f0p = (const uint2*)f0;
    const uint2* f1p = (const uint2*)f1;
    const uint2* f2p = (const uint2*)f2;

    const int tid  = threadIdx.x;
    const int lane = tid & 31;
    const int wid  = tid >> 5;
    const int o    = blockIdx.y;
    const int g    = lane >> 2;
    const int t    = lane & 3;

    // ---------- prep: weights -> fragment-native bf16 hi/lo interleaved uint4 ----------
    {
        const float* w0 = W0 + (size_t)o * H_ * CIN_;   // [n=h][k=c]
        for (int i = tid; i < 4 * 16 * 32; i += NTH_) {
            int ln = i & 31, jj = (i >> 5) & 15, ss = i >> 9;
            int gg = ln >> 2, tt = ln & 3;
            int n = 8 * jj + gg, k0 = 16 * ss + 2 * tt;
            uint32_t h0, l0, h1, l1;
            split2(w0[n * 64 + k0],     w0[n * 64 + k0 + 1], h0, l0);
            split2(w0[n * 64 + k0 + 8], w0[n * 64 + k0 + 9], h1, l1);
            f0[i] = make_uint4(h0, h1, l0, l1);
        }
        const float* w1 = W1 + (size_t)o * H_ * H_;     // [n=g'][k=h]
        for (int i = tid; i < 8 * 16 * 32; i += NTH_) {
            int ln = i & 31, jj = (i >> 5) & 15, ss = i >> 9;
            int gg = ln >> 2, tt = ln & 3;
            int n = 8 * jj + gg, k0 = 16 * ss + 2 * tt;
            uint32_t h0, l0, h1, l1;
            split2(w1[n * 128 + k0],     w1[n * 128 + k0 + 1], h0, l0);
            split2(w1[n * 128 + k0 + 8], w1[n * 128 + k0 + 9], h1, l1);
            f1[i] = make_uint4(h0, h1, l0, l1);
        }
        const float* w2 = W2 + (size_t)o * F2_ * H_;    // [n=f][k=h]
        for (int i = tid; i < 8 * 2 * 32; i += NTH_) {
            int ln = i & 31, jj = (i >> 5) & 1, ss = i >> 6;
            int gg = ln >> 2, tt = ln & 3;
            int n = 8 * jj + gg, k0 = 16 * ss + 2 * tt;
            uint32_t h0, l0, h1, l1;
            split2(w2[n * 128 + k0],     w2[n * 128 + k0 + 1], h0, l0);
            split2(w2[n * 128 + k0 + 8], w2[n * 128 + k0 + 9], h1, l1);
            f2[i] = make_uint4(h0, h1, l0, l1);
        }
    }
    if (tid < H_) {
        sVec[0 * H_ + tid] = b0[o * H_ + tid];
        sVec[1 * H_ + tid] = g0[o * H_ + tid];
        sVec[2 * H_ + tid] = be0[o * H_ + tid];
        sVec[3 * H_ + tid] = b1[o * H_ + tid];
        sVec[4 * H_ + tid] = g1[o * H_ + tid];
        sVec[5 * H_ + tid] = be1[o * H_ + tid];
        if (tid < F2_) sVec[6 * H_ + tid] = b2[o * F2_ + tid];
    }
    __syncthreads();

    float d[16][4];
    uint32_t ah[8][4];
    uint4* myAL = sAL + wid * (8 * 32) + lane;   // per-thread slots, stride 32 per s

#pragma unroll 1
    for (int it = 0; it < TILES_; it++) {
        const int mt = (blockIdx.x * TILES_ + it) * 256 + wid * 16;  // token base

        // ---- load x rows -> A0 fragments: hi in ah[0..3], lo to SMEM ----
        {
            const float* xr0 = x + (size_t)(mt + g) * CIN_;
            const float* xr1 = x + (size_t)(mt + g + 8) * CIN_;
#pragma unroll
            for (int s = 0; s < 4; s++) {
                int k0 = 16 * s + 2 * t;
                float2 p0 = *(const float2*)(xr0 + k0);
                float2 p1 = *(const float2*)(xr1 + k0);
                float2 q0 = *(const float2*)(xr0 + k0 + 8);
                float2 q1 = *(const float2*)(xr1 + k0 + 8);
                uint32_t l0, l1, l2, l3;
                split2(p0.x, p0.y, ah[s][0], l0);
                split2(p1.x, p1.y, ah[s][1], l1);
                split2(q0.x, q0.y, ah[s][2], l2);
                split2(q1.x, q1.y, ah[s][3], l3);
                myAL[s * 32] = make_uint4(l0, l1, l2, l3);
            }
        }

        // ---- GEMM0: M16 N128 K64, pass-major 3-product hi/lo ----
#pragma unroll
        for (int j = 0; j < 16; j++)
#pragma unroll
            for (int q = 0; q < 4; q++) d[j][q] = 0.f;
#pragma unroll
        for (int s = 0; s < 4; s++) {
            const int base = (s * 16) * 32 + lane;
            // pass A: ah . bhi  (16 independent MMAs)
#pragma unroll
            for (int j = 0; j < 16; j++) {
                uint2 bh = f0p[2 * (base + j * 32)];
                MMA2(d[j], ah[s], bh.x, bh.y);
            }
            // pass C: ah . blo
#pragma unroll
            for (int j = 0; j < 16; j++) {
                uint2 bl = f0p[2 * (base + j * 32) + 1];
                MMA2(d[j], ah[s], bl.x, bl.y);
            }
            // pass B: alo . bhi
            uint4 alv = myAL[s * 32];
            uint32_t als[4] = {alv.x, alv.y, alv.z, alv.w};
#pragma unroll
            for (int j = 0; j < 16; j++) {
                uint2 bh = f0p[2 * (base + j * 32)];
                MMA2(d[j], als, bh.x, bh.y);
            }
        }
        ln_repack(d, sVec + 0 * H_, sVec + 1 * H_, sVec + 2 * H_, ah, myAL, t);

        // ---- GEMM1: M16 N128 K128 ----
#pragma unroll
        for (int j = 0; j < 16; j++)
#pragma unroll
            for (int q = 0; q < 4; q++) d[j][q] = 0.f;
#pragma unroll
        for (int s = 0; s < 8; s++) {
            const int base = (s * 16) * 32 + lane;
#pragma unroll
            for (int j = 0; j < 16; j++) {
                uint2 bh = f1p[2 * (base + j * 32)];
                MMA2(d[j], ah[s], bh.x, bh.y);
            }
#pragma unroll
            for (int j = 0; j < 16; j++) {
                uint2 bl = f1p[2 * (base + j * 32) + 1];
                MMA2(d[j], ah[s], bl.x, bl.y);
            }
            uint4 alv = myAL[s * 32];
            uint32_t als[4] = {alv.x, alv.y, alv.z, alv.w};
#pragma unroll
            for (int j = 0; j < 16; j++) {
                uint2 bh = f1p[2 * (base + j * 32)];
                MMA2(d[j], als, bh.x, bh.y);
            }
        }
        ln_repack(d, sVec + 3 * H_, sVec + 4 * H_, sVec + 5 * H_, ah, myAL, t);

        // ---- GEMM2: M16 N16 K128 (interleave passes across s for independence) ----
#pragma unroll
        for (int j = 0; j < 2; j++)
#pragma unroll
            for (int q = 0; q < 4; q++) d[j][q] = 0.f;
#pragma unroll
        for (int s = 0; s < 8; s++) {
            const int base = (s * 2) * 32 + lane;
            uint4 alv = myAL[s * 32];
            uint32_t als[4] = {alv.x, alv.y, alv.z, alv.w};
#pragma unroll
            for (int j = 0; j < 2; j++) {
                uint2 bh = f2p[2 * (base + j * 32)];
                uint2 bl = f2p[2 * (base + j * 32) + 1];
                MMA2(d[j], ah[s], bh.x, bh.y);
                MMA2(d[j], ah[s], bl.x, bl.y);
                MMA2(d[j], als, bh.x, bh.y);
            }
        }

        // ---- output: leaky(D + b2) -> out[(tok*F2 + f)*O + o] ----
        {
            const float* b2s = sVec + 6 * H_;
#pragma unroll
            for (int j = 0; j < 2; j++) {
                int f = 8 * j + 2 * t;
                float2 bb = *(const float2*)(b2s + f);
                float* o0 = out + ((size_t)(mt + g) * F2_ + f) * O_ + o;
                float* o1 = out + ((size_t)(mt + g + 8) * F2_ + f) * O_ + o;
                o0[0]  = leaky_(d[j][0] + bb.x);
                o0[O_] = leaky_(d[j][1] + bb.y);
                o1[0]  = leaky_(d[j][2] + bb.x);
                o1[O_] = leaky_(d[j][3] + bb.y);
            }
        }
    }
}

extern "C" void kernel_launch(void* const* d_in, const int* in_sizes, int n_in,
                              void* d_out, int out_size) {
    const float* x   = (const float*)d_in[0];
    const float* W0  = (const float*)d_in[1];
    const float* b0  = (const float*)d_in[2];
    const float* g0  = (const float*)d_in[3];
    const float* be0 = (const float*)d_in[4];
    const float* W1  = (const float*)d_in[5];
    const float* b1  = (const float*)d_in[6];
    const float* g1  = (const float*)d_in[7];
    const float* be1 = (const float*)d_in[8];
    const float* W2  = (const float*)d_in[9];
    const float* b2  = (const float*)d_in[10];
    float* out = (float*)d_out;

    cudaFuncSetAttribute(film_mma_kernel,
                         cudaFuncAttributeMaxDynamicSharedMemorySize, SMEM_BYTES);
    cudaFuncSetAttribute(film_mma_kernel,
                         cudaFuncAttributePreferredSharedMemoryCarveout, 100);
    dim3 grid(NT_ / (TILES_ * 256), O_);   // (64, 16)
    film_mma_kernel<<<grid, NTH_, SMEM_BYTES>>>(x, W0, b0, g0, be0,
                                                W1, b1, g1, be1, W2, b2, out);
}

// round 7
// speedup vs baseline: 1.2572x; 1.2572x over previous
#include <cuda_runtime.h>
#include <cuda_fp16.h>
#include <cstdint>

#define H_     128
#define CIN_   64
#define O_     16
#define F2_    16
#define NT_    32768
#define TILES_ 2
#define NTH_   512
#define EPS_   1e-5f
#define SLOPE_ 0.01f

// ---- shared memory byte offsets ----
#define SM_W0  0          // [4][16][32] uint2 = 16384  fp16 {b0,b1}
#define SM_W1  16384      // [8][16][32] uint2 = 32768
#define SM_W2  49152      // [8][2][32]  uint2 = 4096
#define SM_VEC 53248      // 784 floats: b0,g0,be0,b1,g1,be1 (128 each) + b2 (16)
#define SM_AL  56384      // [16 warps][8 s][32 lanes] uint4 = 65536
#define SMEM_BYTES (56384 + 65536)

__device__ __forceinline__ float leaky_(float v) { return v >= 0.f ? v : SLOPE_ * v; }

// pack two fp32 -> f16x2 hi (low half = y0) and f16x2 lo (residuals)
__device__ __forceinline__ void split2h(float y0, float y1, uint32_t& hp, uint32_t& lp) {
    uint32_t h;
    asm("cvt.rn.f16x2.f32 %0, %1, %2;" : "=r"(h) : "f"(y1), "f"(y0));
    __half2 hb = *reinterpret_cast<__half2*>(&h);
    float r0 = y0 - __half2float(hb.x);
    float r1 = y1 - __half2float(hb.y);
    asm("cvt.rn.f16x2.f32 %0, %1, %2;" : "=r"(lp) : "f"(r1), "f"(r0));
    hp = h;
}
// single fp16 pack
__device__ __forceinline__ uint32_t pack2h(float y0, float y1) {
    uint32_t h;
    asm("cvt.rn.f16x2.f32 %0, %1, %2;" : "=r"(h) : "f"(y1), "f"(y0));
    return h;
}

#define MMA2(dd, aa, b0, b1)                                                   \
    asm volatile("mma.sync.aligned.m16n8k16.row.col.f32.f16.f16.f32 "         \
                 "{%0,%1,%2,%3}, {%4,%5,%6,%7}, {%8,%9}, {%0,%1,%2,%3};"      \
                 : "+f"((dd)[0]), "+f"((dd)[1]), "+f"((dd)[2]), "+f"((dd)[3]) \
                 : "r"((aa)[0]), "r"((aa)[1]), "r"((aa)[2]), "r"((aa)[3]),    \
                   "r"(b0), "r"(b1))

// LayerNorm + repack: hi fragments -> ah regs, lo fragments -> SMEM (myAL[s*32]).
__device__ __forceinline__ void ln_repack(float (&d)[16][4],
                                          const float* __restrict__ bias,
                                          const float* __restrict__ gam,
                                          const float* __restrict__ bet,
                                          uint32_t (&ah)[8][4],
                                          uint4* __restrict__ myAL,
                                          int t) {
    float s1a = 0.f, s2a = 0.f, s1b = 0.f, s2b = 0.f;
#pragma unroll
    for (int j = 0; j < 16; j++) {
        float2 bb = *(const float2*)(bias + 8 * j + 2 * t);
        float v0 = leaky_(d[j][0] + bb.x);
        float v1 = leaky_(d[j][1] + bb.y);
        float v2 = leaky_(d[j][2] + bb.x);
        float v3 = leaky_(d[j][3] + bb.y);
        d[j][0] = v0; d[j][1] = v1; d[j][2] = v2; d[j][3] = v3;
        s1a += v0 + v1; s2a += v0 * v0 + v1 * v1;
        s1b += v2 + v3; s2b += v2 * v2 + v3 * v3;
    }
#pragma unroll
    for (int off = 1; off <= 2; off <<= 1) {
        s1a += __shfl_xor_sync(0xffffffffu, s1a, off);
        s2a += __shfl_xor_sync(0xffffffffu, s2a, off);
        s1b += __shfl_xor_sync(0xffffffffu, s1b, off);
        s2b += __shfl_xor_sync(0xffffffffu, s2b, off);
    }
    float mua = s1a * (1.f / 128.f);
    float rsa = rsqrtf(fmaxf(s2a * (1.f / 128.f) - mua * mua, 0.f) + EPS_);
    float mub = s1b * (1.f / 128.f);
    float rsb = rsqrtf(fmaxf(s2b * (1.f / 128.f) - mub * mub, 0.f) + EPS_);
#pragma unroll
    for (int s = 0; s < 8; s++) {
        int j0 = 2 * s, j1 = 2 * s + 1;
        float2 g0v = *(const float2*)(gam + 8 * j0 + 2 * t);
        float2 e0v = *(const float2*)(bet + 8 * j0 + 2 * t);
        float2 g1v = *(const float2*)(gam + 8 * j1 + 2 * t);
        float2 e1v = *(const float2*)(bet + 8 * j1 + 2 * t);
        uint32_t l0, l1, l2, l3;
        float y0 = (d[j0][0] - mua) * rsa * g0v.x + e0v.x;
        float y1 = (d[j0][1] - mua) * rsa * g0v.y + e0v.y;
        split2h(y0, y1, ah[s][0], l0);
        y0 = (d[j0][2] - mub) * rsb * g0v.x + e0v.x;
        y1 = (d[j0][3] - mub) * rsb * g0v.y + e0v.y;
        split2h(y0, y1, ah[s][1], l1);
        y0 = (d[j1][0] - mua) * rsa * g1v.x + e1v.x;
        y1 = (d[j1][1] - mua) * rsa * g1v.y + e1v.y;
        split2h(y0, y1, ah[s][2], l2);
        y0 = (d[j1][2] - mub) * rsb * g1v.x + e1v.x;
        y1 = (d[j1][3] - mub) * rsb * g1v.y + e1v.y;
        split2h(y0, y1, ah[s][3], l3);
        myAL[s * 32] = make_uint4(l0, l1, l2, l3);
    }
}

__global__ __launch_bounds__(NTH_, 1)
void film_mma_kernel(const float* __restrict__ x,
                     const float* __restrict__ W0, const float* __restrict__ b0,
                     const float* __restrict__ g0, const float* __restrict__ be0,
                     const float* __restrict__ W1, const float* __restrict__ b1,
                     const float* __restrict__ g1, const float* __restrict__ be1,
                     const float* __restrict__ W2, const float* __restrict__ b2,
                     float* __restrict__ out) {
    extern __shared__ char sp[];
    uint2* f0 = (uint2*)(sp + SM_W0);
    uint2* f1 = (uint2*)(sp + SM_W1);
    uint2* f2 = (uint2*)(sp + SM_W2);
    float* sVec = (float*)(sp + SM_VEC);
    uint4* sAL = (uint4*)(sp + SM_AL);

    const int tid  = threadIdx.x;
    const int lane = tid & 31;
    const int wid  = tid >> 5;
    const int o    = blockIdx.y;
    const int g    = lane >> 2;
    const int t    = lane & 3;

    // ---------- prep: weights -> fragment-native fp16 (single plane) ----------
    {
        const float* w0 = W0 + (size_t)o * H_ * CIN_;   // [n=h][k=c]
        for (int i = tid; i < 4 * 16 * 32; i += NTH_) {
            int ln = i & 31, jj = (i >> 5) & 15, ss = i >> 9;
            int gg = ln >> 2, tt = ln & 3;
            int n = 8 * jj + gg, k0 = 16 * ss + 2 * tt;
            f0[i] = make_uint2(pack2h(w0[n * 64 + k0],     w0[n * 64 + k0 + 1]),
                               pack2h(w0[n * 64 + k0 + 8], w0[n * 64 + k0 + 9]));
        }
        const float* w1 = W1 + (size_t)o * H_ * H_;     // [n=g'][k=h]
        for (int i = tid; i < 8 * 16 * 32; i += NTH_) {
            int ln = i & 31, jj = (i >> 5) & 15, ss = i >> 9;
            int gg = ln >> 2, tt = ln & 3;
            int n = 8 * jj + gg, k0 = 16 * ss + 2 * tt;
            f1[i] = make_uint2(pack2h(w1[n * 128 + k0],     w1[n * 128 + k0 + 1]),
                               pack2h(w1[n * 128 + k0 + 8], w1[n * 128 + k0 + 9]));
        }
        const float* w2 = W2 + (size_t)o * F2_ * H_;    // [n=f][k=h]
        for (int i = tid; i < 8 * 2 * 32; i += NTH_) {
            int ln = i & 31, jj = (i >> 5) & 1, ss = i >> 6;
            int gg = ln >> 2, tt = ln & 3;
            int n = 8 * jj + gg, k0 = 16 * ss + 2 * tt;
            f2[i] = make_uint2(pack2h(w2[n * 128 + k0],     w2[n * 128 + k0 + 1]),
                               pack2h(w2[n * 128 + k0 + 8], w2[n * 128 + k0 + 9]));
        }
    }
    if (tid < H_) {
        sVec[0 * H_ + tid] = b0[o * H_ + tid];
        sVec[1 * H_ + tid] = g0[o * H_ + tid];
        sVec[2 * H_ + tid] = be0[o * H_ + tid];
        sVec[3 * H_ + tid] = b1[o * H_ + tid];
        sVec[4 * H_ + tid] = g1[o * H_ + tid];
        sVec[5 * H_ + tid] = be1[o * H_ + tid];
        if (tid < F2_) sVec[6 * H_ + tid] = b2[o * F2_ + tid];
    }
    __syncthreads();

    float d[16][4];
    uint32_t ah[8][4];
    uint4* myAL = sAL + wid * (8 * 32) + lane;   // per-thread slots, stride 32 per s

#pragma unroll 1
    for (int it = 0; it < TILES_; it++) {
        const int mt = (blockIdx.x * TILES_ + it) * 256 + wid * 16;  // token base

        // ---- load x rows -> A0 fragments: hi in ah[0..3], lo to SMEM ----
        {
            const float* xr0 = x + (size_t)(mt + g) * CIN_;
            const float* xr1 = x + (size_t)(mt + g + 8) * CIN_;
#pragma unroll
            for (int s = 0; s < 4; s++) {
                int k0 = 16 * s + 2 * t;
                float2 p0 = *(const float2*)(xr0 + k0);
                float2 p1 = *(const float2*)(xr1 + k0);
                float2 q0 = *(const float2*)(xr0 + k0 + 8);
                float2 q1 = *(const float2*)(xr1 + k0 + 8);
                uint32_t l0, l1, l2, l3;
                split2h(p0.x, p0.y, ah[s][0], l0);
                split2h(p1.x, p1.y, ah[s][1], l1);
                split2h(q0.x, q0.y, ah[s][2], l2);
                split2h(q1.x, q1.y, ah[s][3], l3);
                myAL[s * 32] = make_uint4(l0, l1, l2, l3);
            }
        }

        // ---- GEMM0: M16 N128 K64, 2-product fp16 hi/lo ----
#pragma unroll
        for (int j = 0; j < 16; j++)
#pragma unroll
            for (int q = 0; q < 4; q++) d[j][q] = 0.f;
#pragma unroll
        for (int s = 0; s < 4; s++) {
            uint4 alv = myAL[s * 32];
            uint32_t als[4] = {alv.x, alv.y, alv.z, alv.w};
#pragma unroll
            for (int j = 0; j < 16; j++) {
                uint2 b = f0[(s * 16 + j) * 32 + lane];
                MMA2(d[j], ah[s], b.x, b.y);
                MMA2(d[j], als,   b.x, b.y);
            }
        }
        ln_repack(d, sVec + 0 * H_, sVec + 1 * H_, sVec + 2 * H_, ah, myAL, t);

        // ---- GEMM1: M16 N128 K128 ----
#pragma unroll
        for (int j = 0; j < 16; j++)
#pragma unroll
            for (int q = 0; q < 4; q++) d[j][q] = 0.f;
#pragma unroll
        for (int s = 0; s < 8; s++) {
            uint4 alv = myAL[s * 32];
            uint32_t als[4] = {alv.x, alv.y, alv.z, alv.w};
#pragma unroll
            for (int j = 0; j < 16; j++) {
                uint2 b = f1[(s * 16 + j) * 32 + lane];
                MMA2(d[j], ah[s], b.x, b.y);
                MMA2(d[j], als,   b.x, b.y);
            }
        }
        ln_repack(d, sVec + 3 * H_, sVec + 4 * H_, sVec + 5 * H_, ah, myAL, t);

        // ---- GEMM2: M16 N16 K128 ----
#pragma unroll
        for (int j = 0; j < 2; j++)
#pragma unroll
            for (int q = 0; q < 4; q++) d[j][q] = 0.f;
#pragma unroll
        for (int s = 0; s < 8; s++) {
            uint4 alv = myAL[s * 32];
            uint32_t als[4] = {alv.x, alv.y, alv.z, alv.w};
#pragma unroll
            for (int j = 0; j < 2; j++) {
                uint2 b = f2[(s * 2 + j) * 32 + lane];
                MMA2(d[j], ah[s], b.x, b.y);
                MMA2(d[j], als,   b.x, b.y);
            }
        }

        // ---- output: leaky(D + b2) -> out[(tok*F2 + f)*O + o] ----
        {
            const float* b2s = sVec + 6 * H_;
#pragma unroll
            for (int j = 0; j < 2; j++) {
                int f = 8 * j + 2 * t;
                float2 bb = *(const float2*)(b2s + f);
                float* o0 = out + ((size_t)(mt + g) * F2_ + f) * O_ + o;
                float* o1 = out + ((size_t)(mt + g + 8) * F2_ + f) * O_ + o;
                o0[0]  = leaky_(d[j][0] + bb.x);
                o0[O_] = leaky_(d[j][1] + bb.y);
                o1[0]  = leaky_(d[j][2] + bb.x);
                o1[O_] = leaky_(d[j][3] + bb.y);
            }
        }
    }
}

extern "C" void kernel_launch(void* const* d_in, const int* in_sizes, int n_in,
                              void* d_out, int out_size) {
    const float* x   = (const float*)d_in[0];
    const float* W0  = (const float*)d_in[1];
    const float* b0  = (const float*)d_in[2];
    const float* g0  = (const float*)d_in[3];
    const float* be0 = (const float*)d_in[4];
    const float* W1  = (const float*)d_in[5];
    const float* b1  = (const float*)d_in[6];
    const float* g1  = (const float*)d_in[7];
    const float* be1 = (const float*)d_in[8];
    const float* W2  = (const float*)d_in[9];
    const float* b2  = (const float*)d_in[10];
    float* out = (float*)d_out;

    cudaFuncSetAttribute(film_mma_kernel,
                         cudaFuncAttributeMaxDynamicSharedMemorySize, SMEM_BYTES);
    cudaFuncSetAttribute(film_mma_kernel,
                         cudaFuncAttributePreferredSharedMemoryCarveout, 100);
    dim3 grid(NT_ / (TILES_ * 256), O_);   // (64, 16)
    film_mma_kernel<<<grid, NTH_, SMEM_BYTES>>>(x, W0, b0, g0, be0,
                                                W1, b1, g1, be1, W2, b2, out);
}

// round 8
// speedup vs baseline: 1.7678x; 1.4061x over previous
#include <cuda_runtime.h>
#include <cuda_fp16.h>
#include <cstdint>

#define H_     128
#define CIN_   64
#define O_     16
#define F2_    16
#define NT_    32768
#define TILES_ 2
#define NTH_   512
#define EPS_   1e-5f
#define SLOPE_ 0.01f

// ---- shared memory byte offsets ----
#define SM_W0  0          // [4][16][32] uint2 = 16384  fp16 {b0,b1}
#define SM_W1  16384      // [8][16][32] uint2 = 32768
#define SM_W2  49152      // [8][2][32]  uint2 = 4096
#define SM_VEC 53248      // 784 floats: b0,g0,be0,b1,g1,be1 (128 each) + b2 (16)
#define SMEM_BYTES (53248 + 784 * 4)

__device__ __forceinline__ float leaky_(float v) { return v >= 0.f ? v : SLOPE_ * v; }

// pack two fp32 -> f16x2 (low half = y0)
__device__ __forceinline__ uint32_t pack2h(float y0, float y1) {
    uint32_t h;
    asm("cvt.rn.f16x2.f32 %0, %1, %2;" : "=r"(h) : "f"(y1), "f"(y0));
    return h;
}

#define MMA2(dd, aa, b0, b1)                                                   \
    asm volatile("mma.sync.aligned.m16n8k16.row.col.f32.f16.f16.f32 "         \
                 "{%0,%1,%2,%3}, {%4,%5,%6,%7}, {%8,%9}, {%0,%1,%2,%3};"      \
                 : "+f"((dd)[0]), "+f"((dd)[1]), "+f"((dd)[2]), "+f"((dd)[3]) \
                 : "r"((aa)[0]), "r"((aa)[1]), "r"((aa)[2]), "r"((aa)[3]),    \
                   "r"(b0), "r"(b1))

// LayerNorm + repack into next A fragments (fp16, single plane, all in regs).
__device__ __forceinline__ void ln_repack(float (&d)[16][4],
                                          const float* __restrict__ bias,
                                          const float* __restrict__ gam,
                                          const float* __restrict__ bet,
                                          uint32_t (&ah)[8][4],
                                          int t) {
    float s1a = 0.f, s2a = 0.f, s1b = 0.f, s2b = 0.f;
#pragma unroll
    for (int j = 0; j < 16; j++) {
        float2 bb = *(const float2*)(bias + 8 * j + 2 * t);
        float v0 = leaky_(d[j][0] + bb.x);
        float v1 = leaky_(d[j][1] + bb.y);
        float v2 = leaky_(d[j][2] + bb.x);
        float v3 = leaky_(d[j][3] + bb.y);
        d[j][0] = v0; d[j][1] = v1; d[j][2] = v2; d[j][3] = v3;
        s1a += v0 + v1; s2a += v0 * v0 + v1 * v1;
        s1b += v2 + v3; s2b += v2 * v2 + v3 * v3;
    }
#pragma unroll
    for (int off = 1; off <= 2; off <<= 1) {
        s1a += __shfl_xor_sync(0xffffffffu, s1a, off);
        s2a += __shfl_xor_sync(0xffffffffu, s2a, off);
        s1b += __shfl_xor_sync(0xffffffffu, s1b, off);
        s2b += __shfl_xor_sync(0xffffffffu, s2b, off);
    }
    float mua = s1a * (1.f / 128.f);
    float rsa = rsqrtf(fmaxf(s2a * (1.f / 128.f) - mua * mua, 0.f) + EPS_);
    float mub = s1b * (1.f / 128.f);
    float rsb = rsqrtf(fmaxf(s2b * (1.f / 128.f) - mub * mub, 0.f) + EPS_);
#pragma unroll
    for (int s = 0; s < 8; s++) {
        int j0 = 2 * s, j1 = 2 * s + 1;
        float2 g0v = *(const float2*)(gam + 8 * j0 + 2 * t);
        float2 e0v = *(const float2*)(bet + 8 * j0 + 2 * t);
        float2 g1v = *(const float2*)(gam + 8 * j1 + 2 * t);
        float2 e1v = *(const float2*)(bet + 8 * j1 + 2 * t);
        ah[s][0] = pack2h((d[j0][0] - mua) * rsa * g0v.x + e0v.x,
                          (d[j0][1] - mua) * rsa * g0v.y + e0v.y);
        ah[s][1] = pack2h((d[j0][2] - mub) * rsb * g0v.x + e0v.x,
                          (d[j0][3] - mub) * rsb * g0v.y + e0v.y);
        ah[s][2] = pack2h((d[j1][0] - mua) * rsa * g1v.x + e1v.x,
                          (d[j1][1] - mua) * rsa * g1v.y + e1v.y);
        ah[s][3] = pack2h((d[j1][2] - mub) * rsb * g1v.x + e1v.x,
                          (d[j1][3] - mub) * rsb * g1v.y + e1v.y);
    }
}

__global__ __launch_bounds__(NTH_, 1)
void film_mma_kernel(const float* __restrict__ x,
                     const float* __restrict__ W0, const float* __restrict__ b0,
                     const float* __restrict__ g0, const float* __restrict__ be0,
                     const float* __restrict__ W1, const float* __restrict__ b1,
                     const float* __restrict__ g1, const float* __restrict__ be1,
                     const float* __restrict__ W2, const float* __restrict__ b2,
                     float* __restrict__ out) {
    extern __shared__ char sp[];
    uint2* f0 = (uint2*)(sp + SM_W0);
    uint2* f1 = (uint2*)(sp + SM_W1);
    uint2* f2 = (uint2*)(sp + SM_W2);
    float* sVec = (float*)(sp + SM_VEC);

    const int tid  = threadIdx.x;
    const int lane = tid & 31;
    const int wid  = tid >> 5;
    const int o    = blockIdx.y;
    const int g    = lane >> 2;
    const int t    = lane & 3;

    // ---------- prep: weights -> fragment-native fp16 (single plane) ----------
    {
        const float* w0 = W0 + (size_t)o * H_ * CIN_;   // [n=h][k=c]
        for (int i = tid; i < 4 * 16 * 32; i += NTH_) {
            int ln = i & 31, jj = (i >> 5) & 15, ss = i >> 9;
            int gg = ln >> 2, tt = ln & 3;
            int n = 8 * jj + gg, k0 = 16 * ss + 2 * tt;
            f0[i] = make_uint2(pack2h(w0[n * 64 + k0],     w0[n * 64 + k0 + 1]),
                               pack2h(w0[n * 64 + k0 + 8], w0[n * 64 + k0 + 9]));
        }
        const float* w1 = W1 + (size_t)o * H_ * H_;     // [n=g'][k=h]
        for (int i = tid; i < 8 * 16 * 32; i += NTH_) {
            int ln = i & 31, jj = (i >> 5) & 15, ss = i >> 9;
            int gg = ln >> 2, tt = ln & 3;
            int n = 8 * jj + gg, k0 = 16 * ss + 2 * tt;
            f1[i] = make_uint2(pack2h(w1[n * 128 + k0],     w1[n * 128 + k0 + 1]),
                               pack2h(w1[n * 128 + k0 + 8], w1[n * 128 + k0 + 9]));
        }
        const float* w2 = W2 + (size_t)o * F2_ * H_;    // [n=f][k=h]
        for (int i = tid; i < 8 * 2 * 32; i += NTH_) {
            int ln = i & 31, jj = (i >> 5) & 1, ss = i >> 6;
            int gg = ln >> 2, tt = ln & 3;
            int n = 8 * jj + gg, k0 = 16 * ss + 2 * tt;
            f2[i] = make_uint2(pack2h(w2[n * 128 + k0],     w2[n * 128 + k0 + 1]),
                               pack2h(w2[n * 128 + k0 + 8], w2[n * 128 + k0 + 9]));
        }
    }
    if (tid < H_) {
        sVec[0 * H_ + tid] = b0[o * H_ + tid];
        sVec[1 * H_ + tid] = g0[o * H_ + tid];
        sVec[2 * H_ + tid] = be0[o * H_ + tid];
        sVec[3 * H_ + tid] = b1[o * H_ + tid];
        sVec[4 * H_ + tid] = g1[o * H_ + tid];
        sVec[5 * H_ + tid] = be1[o * H_ + tid];
        if (tid < F2_) sVec[6 * H_ + tid] = b2[o * F2_ + tid];
    }
    __syncthreads();

    float d[16][4];
    uint32_t ah[8][4];

#pragma unroll 1
    for (int it = 0; it < TILES_; it++) {
        const int mt = (blockIdx.x * TILES_ + it) * 256 + wid * 16;  // token base

        // ---- load x rows -> A0 fragments (fp16) ----
        {
            const float* xr0 = x + (size_t)(mt + g) * CIN_;
            const float* xr1 = x + (size_t)(mt + g + 8) * CIN_;
#pragma unroll
            for (int s = 0; s < 4; s++) {
                int k0 = 16 * s + 2 * t;
                float2 p0 = *(const float2*)(xr0 + k0);
                float2 p1 = *(const float2*)(xr1 + k0);
                float2 q0 = *(const float2*)(xr0 + k0 + 8);
                float2 q1 = *(const float2*)(xr1 + k0 + 8);
                ah[s][0] = pack2h(p0.x, p0.y);
                ah[s][1] = pack2h(p1.x, p1.y);
                ah[s][2] = pack2h(q0.x, q0.y);
                ah[s][3] = pack2h(q1.x, q1.y);
            }
        }

        // ---- GEMM0: M16 N128 K64, single-product fp16 ----
#pragma unroll
        for (int j = 0; j < 16; j++)
#pragma unroll
            for (int q = 0; q < 4; q++) d[j][q] = 0.f;
#pragma unroll
        for (int s = 0; s < 4; s++) {
#pragma unroll
            for (int j = 0; j < 16; j++) {
                uint2 b = f0[(s * 16 + j) * 32 + lane];
                MMA2(d[j], ah[s], b.x, b.y);
            }
        }
        ln_repack(d, sVec + 0 * H_, sVec + 1 * H_, sVec + 2 * H_, ah, t);

        // ---- GEMM1: M16 N128 K128 ----
#pragma unroll
        for (int j = 0; j < 16; j++)
#pragma unroll
            for (int q = 0; q < 4; q++) d[j][q] = 0.f;
#pragma unroll
        for (int s = 0; s < 8; s++) {
#pragma unroll
            for (int j = 0; j < 16; j++) {
                uint2 b = f1[(s * 16 + j) * 32 + lane];
                MMA2(d[j], ah[s], b.x, b.y);
            }
        }
        ln_repack(d, sVec + 3 * H_, sVec + 4 * H_, sVec + 5 * H_, ah, t);

        // ---- GEMM2: M16 N16 K128 ----
#pragma unroll
        for (int j = 0; j < 2; j++)
#pragma unroll
            for (int q = 0; q < 4; q++) d[j][q] = 0.f;
#pragma unroll
        for (int s = 0; s < 8; s++) {
#pragma unroll
            for (int j = 0; j < 2; j++) {
                uint2 b = f2[(s * 2 + j) * 32 + lane];
                MMA2(d[j], ah[s], b.x, b.y);
            }
        }

        // ---- output: leaky(D + b2) -> out[(tok*F2 + f)*O + o] ----
        {
            const float* b2s = sVec + 6 * H_;
#pragma unroll
            for (int j = 0; j < 2; j++) {
                int f = 8 * j + 2 * t;
                float2 bb = *(const float2*)(b2s + f);
                float* o0 = out + ((size_t)(mt + g) * F2_ + f) * O_ + o;
                float* o1 = out + ((size_t)(mt + g + 8) * F2_ + f) * O_ + o;
                o0[0]  = leaky_(d[j][0] + bb.x);
                o0[O_] = leaky_(d[j][1] + bb.y);
                o1[0]  = leaky_(d[j][2] + bb.x);
                o1[O_] = leaky_(d[j][3] + bb.y);
            }
        }
    }
}

extern "C" void kernel_launch(void* const* d_in, const int* in_sizes, int n_in,
                              void* d_out, int out_size) {
    const float* x   = (const float*)d_in[0];
    const float* W0  = (const float*)d_in[1];
    const float* b0  = (const float*)d_in[2];
    const float* g0  = (const float*)d_in[3];
    const float* be0 = (const float*)d_in[4];
    const float* W1  = (const float*)d_in[5];
    const float* b1  = (const float*)d_in[6];
    const float* g1  = (const float*)d_in[7];
    const float* be1 = (const float*)d_in[8];
    const float* W2  = (const float*)d_in[9];
    const float* b2  = (const float*)d_in[10];
    float* out = (float*)d_out;

    cudaFuncSetAttribute(film_mma_kernel,
                         cudaFuncAttributeMaxDynamicSharedMemorySize, SMEM_BYTES);
    cudaFuncSetAttribute(film_mma_kernel,
                         cudaFuncAttributePreferredSharedMemoryCarveout, 100);
    dim3 grid(NT_ / (TILES_ * 256), O_);   // (64, 16)
    film_mma_kernel<<<grid, NTH_, SMEM_BYTES>>>(x, W0, b0, g0, be0,
                                                W1, b1, g1, be1, W2, b2, out);
}